// round 4
// baseline (speedup 1.0000x reference)
#include <cuda_runtime.h>
#include <math.h>

#define DD   256
#define DD3  768

// ---------------- device scratch (no allocations allowed) ----------------
__device__ float g_sub[DD];                 // seed subject embedding
__device__ float g_gi[DD3];                 // gi = r0 @ W_ih.T + b_ih
__device__ float g_WhhT[DD * DD3];          // W_hh transposed: [k][j]
__device__ float g_objWT[DD * DD];          // obj_W transposed: [k][j]
__device__ float g_gh[1024 * DD3];          // rel_emb @ W_hh.T + b_hh   [R,768]
__device__ float g_rj[1024 * DD];           // GRU output per relation    [R,256]
__device__ float g_objTable[1024 * DD];     // obj embedding per relation [R,256]
__device__ int   g_map[1 << 19];            // node -> edge inverse map (N <= 524288)

__device__ __forceinline__ float sigm(float x) { return 1.0f / (1.0f + expf(-x)); }

// ---------------- merged transposes ----------------
__global__ void transpose_kernel(const float* __restrict__ W_hh,
                                 const float* __restrict__ obj_W) {
    __shared__ float tile[32][33];
    int bx = blockIdx.x, by = blockIdx.y;
    if (by < 24) {
        int x = bx * 32 + threadIdx.x;
        int y = by * 32 + threadIdx.y;
        tile[threadIdx.y][threadIdx.x] = W_hh[y * DD + x];
        __syncthreads();
        int oj = by * 32 + threadIdx.x;
        int ok = bx * 32 + threadIdx.y;
        g_WhhT[ok * DD3 + oj] = tile[threadIdx.x][threadIdx.y];
    } else {
        int byy = by - 24;
        int x = bx * 32 + threadIdx.x;
        int y = byy * 32 + threadIdx.y;
        tile[threadIdx.y][threadIdx.x] = obj_W[y * DD + x];
        __syncthreads();
        int oj = byy * 32 + threadIdx.x;
        int ok = bx * 32 + threadIdx.y;
        g_objWT[ok * DD + oj] = tile[threadIdx.x][threadIdx.y];
    }
}

// ---------------- serial chain: sub -> r0 -> gi  (single block) ----------------
__global__ void __launch_bounds__(DD3) prep_kernel(
    const float* __restrict__ enc, const float* __restrict__ mask,
    const float* __restrict__ W_ih, const float* __restrict__ W_hh,
    const float* __restrict__ b_ih, const float* __restrict__ b_hh,
    const float* __restrict__ sub_W, const float* __restrict__ sub_b)
{
    __shared__ float sm_mask[DD], sm_enc[DD], sm_sub[DD], sm_r0[DD];
    __shared__ float sm_gi0[DD3], sm_gh0[DD3];
    int t = threadIdx.x;

    if (t < DD) { sm_mask[t] = mask[t]; sm_enc[t] = enc[t]; }
    __syncthreads();

    if (t < DD) {
        float a = sub_b[t];
        const float4* w = (const float4*)(sub_W + t * DD);
        const float4* m = (const float4*)sm_mask;
        #pragma unroll 8
        for (int k = 0; k < DD / 4; k++) {
            float4 wv = w[k]; float4 mv = m[k];
            a += mv.x * wv.x + mv.y * wv.y + mv.z * wv.z + mv.w * wv.w;
        }
        float s = tanhf(a);
        sm_sub[t] = s;
        g_sub[t] = s;
    }
    __syncthreads();

    {
        float a = b_ih[t], b = b_hh[t];
        const float4* wi = (const float4*)(W_ih + t * DD);
        const float4* wh = (const float4*)(W_hh + t * DD);
        const float4* ev = (const float4*)sm_enc;
        const float4* sv = (const float4*)sm_sub;
        #pragma unroll 8
        for (int k = 0; k < DD / 4; k++) {
            float4 w1 = wi[k], e4 = ev[k];
            a += e4.x * w1.x + e4.y * w1.y + e4.z * w1.z + e4.w * w1.w;
            float4 w2 = wh[k], s4 = sv[k];
            b += s4.x * w2.x + s4.y * w2.y + s4.z * w2.z + s4.w * w2.w;
        }
        sm_gi0[t] = a; sm_gh0[t] = b;
    }
    __syncthreads();

    if (t < DD) {
        float r = sigm(sm_gi0[t] + sm_gh0[t]);
        float z = sigm(sm_gi0[DD + t] + sm_gh0[DD + t]);
        float n = tanhf(sm_gi0[2 * DD + t] + r * sm_gh0[2 * DD + t]);
        sm_r0[t] = (1.0f - z) * n + z * sm_sub[t];
    }
    __syncthreads();

    {
        float a = b_ih[t];
        const float4* wi = (const float4*)(W_ih + t * DD);
        const float4* rv = (const float4*)sm_r0;
        #pragma unroll 8
        for (int k = 0; k < DD / 4; k++) {
            float4 wv = wi[k]; float4 r4 = rv[k];
            a += r4.x * wv.x + r4.y * wv.y + r4.z * wv.z + r4.w * wv.w;
        }
        g_gi[t] = a;
    }
}

// ---------------- node -> edge inverse map ----------------
__global__ void __launch_bounds__(512) map_init_kernel(int N) {
    int i = blockIdx.x * blockDim.x + threadIdx.x;
    if (i < N) g_map[i] = -1;
}
__global__ void __launch_bounds__(512) map_scatter_kernel(const int* __restrict__ tail_ids, int E) {
    int e = blockIdx.x * blockDim.x + threadIdx.x;
    if (e < E) g_map[tail_ids[e]] = e;
}

// ---------------- tiled GEMM: C[M,NCOLS] = A[M,256] @ B[256,NCOLS] + bias (+tanh) ----------------
template<int NCOLS, bool DOTANH>
__global__ void __launch_bounds__(256) gemm_kernel(
    const float* __restrict__ A, const float* __restrict__ B,
    const float* __restrict__ bias, float* __restrict__ C, int M)
{
    __shared__ float As[64][36];
    __shared__ float Bs[32][68];
    int tid = threadIdx.x;
    int tx = tid & 15, ty = tid >> 4;
    int rbase = blockIdx.y * 64;
    int cbase = blockIdx.x * 64;
    float acc[4][4] = {};

    for (int k0 = 0; k0 < DD; k0 += 32) {
        #pragma unroll
        for (int i = 0; i < 2; i++) {
            int idx = tid + i * 256;
            int ar = idx >> 3;
            int ac = (idx & 7) << 2;
            int gr = rbase + ar;
            float4 av = (gr < M) ? *(const float4*)(A + (size_t)gr * DD + k0 + ac)
                                 : make_float4(0.f, 0.f, 0.f, 0.f);
            *(float4*)&As[ar][ac] = av;
            int bk = idx >> 4;
            int bc = (idx & 15) << 2;
            float4 bv = *(const float4*)(B + (size_t)(k0 + bk) * NCOLS + cbase + bc);
            *(float4*)&Bs[bk][bc] = bv;
        }
        __syncthreads();
        #pragma unroll
        for (int kk = 0; kk < 32; kk++) {
            float a0 = As[ty * 4 + 0][kk];
            float a1 = As[ty * 4 + 1][kk];
            float a2 = As[ty * 4 + 2][kk];
            float a3 = As[ty * 4 + 3][kk];
            float4 b = *(const float4*)&Bs[kk][tx * 4];
            acc[0][0] = fmaf(a0, b.x, acc[0][0]); acc[0][1] = fmaf(a0, b.y, acc[0][1]);
            acc[0][2] = fmaf(a0, b.z, acc[0][2]); acc[0][3] = fmaf(a0, b.w, acc[0][3]);
            acc[1][0] = fmaf(a1, b.x, acc[1][0]); acc[1][1] = fmaf(a1, b.y, acc[1][1]);
            acc[1][2] = fmaf(a1, b.z, acc[1][2]); acc[1][3] = fmaf(a1, b.w, acc[1][3]);
            acc[2][0] = fmaf(a2, b.x, acc[2][0]); acc[2][1] = fmaf(a2, b.y, acc[2][1]);
            acc[2][2] = fmaf(a2, b.z, acc[2][2]); acc[2][3] = fmaf(a2, b.w, acc[2][3]);
            acc[3][0] = fmaf(a3, b.x, acc[3][0]); acc[3][1] = fmaf(a3, b.y, acc[3][1]);
            acc[3][2] = fmaf(a3, b.z, acc[3][2]); acc[3][3] = fmaf(a3, b.w, acc[3][3]);
        }
        __syncthreads();
    }

    int col = cbase + tx * 4;
    float4 bv = *(const float4*)(bias + col);
    #pragma unroll
    for (int i = 0; i < 4; i++) {
        int gr = rbase + ty * 4 + i;
        if (gr < M) {
            float4 v;
            v.x = acc[i][0] + bv.x; v.y = acc[i][1] + bv.y;
            v.z = acc[i][2] + bv.z; v.w = acc[i][3] + bv.w;
            if (DOTANH) { v.x = tanhf(v.x); v.y = tanhf(v.y); v.z = tanhf(v.z); v.w = tanhf(v.w); }
            *(float4*)(C + (size_t)gr * NCOLS + col) = v;
        }
    }
}

// ---------------- elementwise GRU gate combine ----------------
__global__ void __launch_bounds__(256) combine_kernel(const float* __restrict__ rel_table, int R) {
    int idx = blockIdx.x * blockDim.x + threadIdx.x;
    if (idx >= R * DD) return;
    int r = idx >> 8, t = idx & 255;
    const float* gh = g_gh + (size_t)r * DD3;
    float rr = sigm(g_gi[t] + gh[t]);
    float zz = sigm(g_gi[DD + t] + gh[DD + t]);
    float nn = tanhf(g_gi[2 * DD + t] + rr * gh[2 * DD + t]);
    g_rj[idx] = (1.0f - zz) * nn + zz * rel_table[idx];
}

// ---------------- assembleA: entity-gather / seed / zero rows (independent of GEMMs)
__global__ void __launch_bounds__(256) assembleA_kernel(
    float* __restrict__ out,
    const float* __restrict__ entity_table,
    const int* __restrict__ tails_state,
    const int* __restrict__ origin_ids,
    const int* __restrict__ seed_p,
    int N)
{
    long long gid = (long long)blockIdx.x * blockDim.x + threadIdx.x;
    int lane = (int)(gid & 63);
    long long n = gid >> 6;
    if (n >= N) return;

    int e = g_map[n];
    float4 v;
    if (e >= 0) {
        if (__ldg(tails_state + e) != 1) return;          // obj row: assembleB's job
        const float4* src = (const float4*)(entity_table + (size_t)__ldg(origin_ids + e) * DD);
        v = __ldcs(src + lane);
    } else if ((int)n == *seed_p) {
        v = ((const float4*)g_sub)[lane];
    } else {
        v = make_float4(0.f, 0.f, 0.f, 0.f);
    }
    __stcs((float4*)out + n * (DD / 4) + lane, v);
}

// ---------------- assembleB: obj rows (needs objTable) ----------------
__global__ void __launch_bounds__(256) assembleB_kernel(
    float* __restrict__ out,
    const int* __restrict__ rel_ids,
    const int* __restrict__ tails_state,
    int N)
{
    long long gid = (long long)blockIdx.x * blockDim.x + threadIdx.x;
    int lane = (int)(gid & 63);
    long long n = gid >> 6;
    if (n >= N) return;

    int e = g_map[n];
    if (e < 0 || __ldg(tails_state + e) == 1) return;     // not an obj row
    const float4* src = (const float4*)(g_objTable + (size_t)__ldg(rel_ids + e) * DD);
    float4 v = src[lane];                                  // 1MB table: L2-resident
    __stcs((float4*)out + n * (DD / 4) + lane, v);
}

// ---------------- launch ----------------
extern "C" void kernel_launch(void* const* d_in, const int* in_sizes, int n_in,
                              void* d_out, int out_size)
{
    const float* enc          = (const float*)d_in[0];
    const float* mask         = (const float*)d_in[1];
    const float* entity_table = (const float*)d_in[2];
    const float* rel_table    = (const float*)d_in[3];
    const float* W_ih         = (const float*)d_in[4];
    const float* W_hh         = (const float*)d_in[5];
    const float* b_ih         = (const float*)d_in[6];
    const float* b_hh         = (const float*)d_in[7];
    const float* sub_W        = (const float*)d_in[8];
    const float* sub_b        = (const float*)d_in[9];
    const float* obj_W        = (const float*)d_in[10];
    const float* obj_b        = (const float*)d_in[11];
    const int*   rel_ids      = (const int*)d_in[12];
    const int*   tail_ids     = (const int*)d_in[13];
    const int*   tails_state  = (const int*)d_in[14];
    const int*   origin_ids   = (const int*)d_in[15];
    const int*   seed_p       = (const int*)d_in[16];
    float*       out          = (float*)d_out;

    int E = in_sizes[12];
    int R = in_sizes[3] / DD;
    int N = out_size / DD;

    // Lazy one-time stream/event creation (happens on first correctness call,
    // NOT during graph capture; no device memory involved).
    static cudaStream_t s1 = nullptr;
    static cudaEvent_t evFork = nullptr, evPrep = nullptr, evMap = nullptr, evJoin = nullptr;
    if (!s1) {
        cudaStreamCreateWithFlags(&s1, cudaStreamNonBlocking);
        cudaEventCreateWithFlags(&evFork, cudaEventDisableTiming);
        cudaEventCreateWithFlags(&evPrep, cudaEventDisableTiming);
        cudaEventCreateWithFlags(&evMap,  cudaEventDisableTiming);
        cudaEventCreateWithFlags(&evJoin, cudaEventDisableTiming);
    }

    float *ghp, *whp, *rjp, *owp, *otp;
    cudaGetSymbolAddress((void**)&ghp, g_gh);
    cudaGetSymbolAddress((void**)&whp, g_WhhT);
    cudaGetSymbolAddress((void**)&rjp, g_rj);
    cudaGetSymbolAddress((void**)&owp, g_objWT);
    cudaGetSymbolAddress((void**)&otp, g_objTable);

    long long rowThreads = (long long)N * 64;
    int asmBlocks = (int)((rowThreads + 255) / 256);

    // ---- fork s1 off the capture (default) stream ----
    cudaEventRecord(evFork, 0);
    cudaStreamWaitEvent(s1, evFork, 0);

    // ---- s0: prep chain -> transposes -> GEMM pipeline ----
    prep_kernel<<<1, DD3>>>(enc, mask, W_ih, W_hh, b_ih, b_hh, sub_W, sub_b);
    cudaEventRecord(evPrep, 0);
    transpose_kernel<<<dim3(8, 32), dim3(32, 32)>>>(W_hh, obj_W);
    gemm_kernel<DD3, false><<<dim3(DD3 / 64, (R + 63) / 64), 256>>>(rel_table, whp, b_hh, ghp, R);
    combine_kernel<<<(R * DD + 255) / 256, 256>>>(rel_table, R);
    gemm_kernel<DD, true><<<dim3(DD / 64, (R + 63) / 64), 256>>>(rjp, owp, obj_b, otp, R);

    // ---- s1: map build, then the big DRAM-bound assembleA (overlaps GEMM path) ----
    map_init_kernel<<<(N + 511) / 512, 512, 0, s1>>>(N);
    map_scatter_kernel<<<(E + 511) / 512, 512, 0, s1>>>(tail_ids, E);
    cudaEventRecord(evMap, s1);
    cudaStreamWaitEvent(s1, evPrep, 0);   // needs g_sub for the seed row
    assembleA_kernel<<<asmBlocks, 256, 0, s1>>>(out, entity_table, tails_state,
                                                origin_ids, seed_p, N);

    // ---- s0: obj rows once objTable + map are ready (overlaps assembleA) ----
    cudaStreamWaitEvent(0, evMap, 0);
    assembleB_kernel<<<asmBlocks, 256>>>(out, rel_ids, tails_state, N);

    // ---- join s1 back into the capture stream ----
    cudaEventRecord(evJoin, s1);
    cudaStreamWaitEvent(0, evJoin, 0);
}

// round 6
// speedup vs baseline: 2.2431x; 2.2431x over previous
#include <cuda_runtime.h>
#include <math.h>

#define DD   256
#define DD3  768
#define OBJ_FLAG 0x40000000

// ---------------- device scratch ----------------
__device__ float g_sub[DD];                 // seed subject embedding
__device__ float g_gi0[DD3];                // enc @ W_ih.T + b_ih
__device__ float g_gh0[DD3];                // sub @ W_hh.T + b_hh
__device__ float g_gi[DD3];                 // r0 @ W_ih.T + b_ih (broadcast gi for all edges)
__device__ float g_WhhT[DD * DD3];          // W_hh transposed
__device__ float g_objWT[DD * DD];          // obj_W transposed
__device__ float g_gh[1024 * DD3];          // rel GEMM output [R,768]
__device__ float g_rj[1024 * DD];           // GRU output per relation [R,256]
__device__ float g_objTable[1024 * DD];     // obj embedding per relation [R,256]
__device__ int   g_src[1 << 19];            // node -> source descriptor

__device__ __forceinline__ float sigm(float x) { return 1.0f / (1.0f + expf(-x)); }

// ---------------- fused: transposes + g_src init + seed mark ----------------
// blocks 0..255: transpose (32x32 tiles); blocks 256..: init g_src
__global__ void __launch_bounds__(1024) init_kernel(
    const float* __restrict__ W_hh, const float* __restrict__ obj_W,
    const int* __restrict__ seed_p, int N)
{
    int b = blockIdx.x;
    if (b < 256) {
        __shared__ float tile[32][33];
        int bx = b & 7, by = b >> 3;
        if (by < 24) {
            int x = bx * 32 + threadIdx.x;
            int y = by * 32 + threadIdx.y;
            tile[threadIdx.y][threadIdx.x] = W_hh[y * DD + x];
            __syncthreads();
            int oj = by * 32 + threadIdx.x;
            int ok = bx * 32 + threadIdx.y;
            g_WhhT[ok * DD3 + oj] = tile[threadIdx.x][threadIdx.y];
        } else {
            int byy = by - 24;
            int x = bx * 32 + threadIdx.x;
            int y = byy * 32 + threadIdx.y;
            tile[threadIdx.y][threadIdx.x] = obj_W[y * DD + x];
            __syncthreads();
            int oj = byy * 32 + threadIdx.x;
            int ok = bx * 32 + threadIdx.y;
            g_objWT[ok * DD + oj] = tile[threadIdx.x][threadIdx.y];
        }
    } else {
        int tid = threadIdx.y * 32 + threadIdx.x;
        int i = (b - 256) * 1024 + tid;
        if (i < N) {
            int sd = __ldg(seed_p);
            g_src[i] = (i == sd) ? -2 : -1;
        }
    }
}

// ---------------- warp-per-row matvec stages ----------------
// Stage A: sub = tanh(sub_W @ mask + sub_b)   (256 rows)
__global__ void __launch_bounds__(256) matvecA_kernel(
    const float* __restrict__ mask, const float* __restrict__ sub_W,
    const float* __restrict__ sub_b)
{
    __shared__ float4 xv[64];
    int tid = threadIdx.x, lane = tid & 31, warp = tid >> 5;
    if (tid < 64) xv[tid] = ((const float4*)mask)[tid];
    __syncthreads();
    int row = blockIdx.x * 8 + warp;
    const float4* w = (const float4*)(sub_W + (size_t)row * DD);
    float acc = 0.f;
    #pragma unroll
    for (int i = 0; i < 2; i++) {
        int k = lane + i * 32;
        float4 wv = w[k], x4 = xv[k];
        acc += wv.x * x4.x + wv.y * x4.y + wv.z * x4.z + wv.w * x4.w;
    }
    #pragma unroll
    for (int o = 16; o > 0; o >>= 1) acc += __shfl_down_sync(~0u, acc, o);
    if (lane == 0) g_sub[row] = tanhf(acc + sub_b[row]);
}

// Stage B: gi0 = W_ih@enc + b_ih (rows 0..767), gh0 = W_hh@sub + b_hh (rows 768..1535)
__global__ void __launch_bounds__(256) matvecB_kernel(
    const float* __restrict__ enc,
    const float* __restrict__ W_ih, const float* __restrict__ W_hh,
    const float* __restrict__ b_ih, const float* __restrict__ b_hh)
{
    __shared__ float4 xe[64], xs[64];
    int tid = threadIdx.x, lane = tid & 31, warp = tid >> 5;
    if (tid < 64) { xe[tid] = ((const float4*)enc)[tid]; xs[tid] = ((const float4*)g_sub)[tid]; }
    __syncthreads();
    int grow = blockIdx.x * 8 + warp;            // 0..1535
    bool isB = grow >= DD3;
    int row = isB ? grow - DD3 : grow;
    const float4* w = (const float4*)((isB ? W_hh : W_ih) + (size_t)row * DD);
    const float4* xv = isB ? xs : xe;
    float acc = 0.f;
    #pragma unroll
    for (int i = 0; i < 2; i++) {
        int k = lane + i * 32;
        float4 wv = w[k], x4 = xv[k];
        acc += wv.x * x4.x + wv.y * x4.y + wv.z * x4.z + wv.w * x4.w;
    }
    #pragma unroll
    for (int o = 16; o > 0; o >>= 1) acc += __shfl_down_sync(~0u, acc, o);
    if (lane == 0) {
        if (isB) g_gh0[row] = acc + b_hh[row];
        else     g_gi0[row] = acc + b_ih[row];
    }
}

// Stage D: r0 (recomputed per block, elementwise) then gi = W_ih@r0 + b_ih (768 rows)
__global__ void __launch_bounds__(256) matvecD_kernel(
    const float* __restrict__ W_ih, const float* __restrict__ b_ih)
{
    __shared__ float r0s[DD];
    int tid = threadIdx.x, lane = tid & 31, warp = tid >> 5;
    // recompute r0 (cheap, 256 elementwise ops)
    {
        float gi_r = g_gi0[tid],      gh_r = g_gh0[tid];
        float gi_z = g_gi0[DD + tid], gh_z = g_gh0[DD + tid];
        float gi_n = g_gi0[2*DD + tid], gh_n = g_gh0[2*DD + tid];
        float r = sigm(gi_r + gh_r);
        float z = sigm(gi_z + gh_z);
        float n = tanhf(gi_n + r * gh_n);
        r0s[tid] = (1.0f - z) * n + z * g_sub[tid];
    }
    __syncthreads();
    int row = blockIdx.x * 8 + warp;             // 0..767
    const float4* w = (const float4*)(W_ih + (size_t)row * DD);
    const float4* xv = (const float4*)r0s;
    float acc = 0.f;
    #pragma unroll
    for (int i = 0; i < 2; i++) {
        int k = lane + i * 32;
        float4 wv = w[k], x4 = xv[k];
        acc += wv.x * x4.x + wv.y * x4.y + wv.z * x4.z + wv.w * x4.w;
    }
    #pragma unroll
    for (int o = 16; o > 0; o >>= 1) acc += __shfl_down_sync(~0u, acc, o);
    if (lane == 0) g_gi[row] = acc + b_ih[row];
}

// ---------------- scatter: resolve per-edge source descriptor (coalesced reads) ----------------
__global__ void __launch_bounds__(512) scatter_kernel(
    const int* __restrict__ tail_ids, const int* __restrict__ tails_state,
    const int* __restrict__ origin_ids, const int* __restrict__ rel_ids, int E)
{
    int e = blockIdx.x * blockDim.x + threadIdx.x;
    if (e >= E) return;
    int code = (__ldg(tails_state + e) == 1) ? __ldg(origin_ids + e)
                                             : (__ldg(rel_ids + e) | OBJ_FLAG);
    g_src[__ldg(tail_ids + e)] = code;
}

// ---------------- tiled GEMM 32x64: C[M,NCOLS] = A[M,256] @ B[256,NCOLS] + bias (+tanh)
template<int NCOLS, bool DOTANH>
__global__ void __launch_bounds__(256) gemm_kernel(
    const float* __restrict__ A, const float* __restrict__ B,
    const float* __restrict__ bias, float* __restrict__ C, int M)
{
    __shared__ float As[32][36];
    __shared__ float Bs[32][68];
    int tid = threadIdx.x;
    int tx = tid & 15, ty = tid >> 4;            // tx: 4 cols, ty: 2 rows
    int rbase = blockIdx.y * 32;
    int cbase = blockIdx.x * 64;
    float acc[2][4] = {};

    for (int k0 = 0; k0 < DD; k0 += 32) {
        {   // A tile: 32 rows x 32 k = 256 float4, one per thread
            int ar = tid >> 3;
            int ac = (tid & 7) << 2;
            int gr = rbase + ar;
            float4 av = (gr < M) ? *(const float4*)(A + (size_t)gr * DD + k0 + ac)
                                 : make_float4(0.f, 0.f, 0.f, 0.f);
            *(float4*)&As[ar][ac] = av;
        }
        #pragma unroll
        for (int i = 0; i < 2; i++) {            // B tile: 32 k x 64 cols = 512 float4
            int idx = tid + i * 256;
            int bk = idx >> 4;
            int bc = (idx & 15) << 2;
            float4 bv = *(const float4*)(B + (size_t)(k0 + bk) * NCOLS + cbase + bc);
            *(float4*)&Bs[bk][bc] = bv;
        }
        __syncthreads();
        #pragma unroll
        for (int kk = 0; kk < 32; kk++) {
            float a0 = As[ty * 2 + 0][kk];
            float a1 = As[ty * 2 + 1][kk];
            float4 b = *(const float4*)&Bs[kk][tx * 4];
            acc[0][0] = fmaf(a0, b.x, acc[0][0]); acc[0][1] = fmaf(a0, b.y, acc[0][1]);
            acc[0][2] = fmaf(a0, b.z, acc[0][2]); acc[0][3] = fmaf(a0, b.w, acc[0][3]);
            acc[1][0] = fmaf(a1, b.x, acc[1][0]); acc[1][1] = fmaf(a1, b.y, acc[1][1]);
            acc[1][2] = fmaf(a1, b.z, acc[1][2]); acc[1][3] = fmaf(a1, b.w, acc[1][3]);
        }
        __syncthreads();
    }

    int col = cbase + tx * 4;
    float4 bv = *(const float4*)(bias + col);
    #pragma unroll
    for (int i = 0; i < 2; i++) {
        int gr = rbase + ty * 2 + i;
        if (gr < M) {
            float4 v;
            v.x = acc[i][0] + bv.x; v.y = acc[i][1] + bv.y;
            v.z = acc[i][2] + bv.z; v.w = acc[i][3] + bv.w;
            if (DOTANH) { v.x = tanhf(v.x); v.y = tanhf(v.y); v.z = tanhf(v.z); v.w = tanhf(v.w); }
            *(float4*)(C + (size_t)gr * NCOLS + col) = v;
        }
    }
}

// ---------------- GRU gate combine (float4) ----------------
__global__ void __launch_bounds__(256) combine_kernel(const float* __restrict__ rel_table, int R) {
    int idx = blockIdx.x * blockDim.x + threadIdx.x;   // float4 units
    if (idx >= R * 64) return;
    int r = idx >> 6, t4 = idx & 63;
    const float4* gi4 = (const float4*)g_gi;
    const float4* gh4 = (const float4*)(g_gh + (size_t)r * DD3);
    float4 gir = gi4[t4],        ghr = gh4[t4];
    float4 giz = gi4[64 + t4],   ghz = gh4[64 + t4];
    float4 gin = gi4[128 + t4],  ghn = gh4[128 + t4];
    float4 h   = ((const float4*)rel_table)[(size_t)r * 64 + t4];
    float4 o;
    {
        float rr = sigm(gir.x + ghr.x), zz = sigm(giz.x + ghz.x);
        float nn = tanhf(gin.x + rr * ghn.x);
        o.x = (1.f - zz) * nn + zz * h.x;
    }
    {
        float rr = sigm(gir.y + ghr.y), zz = sigm(giz.y + ghz.y);
        float nn = tanhf(gin.y + rr * ghn.y);
        o.y = (1.f - zz) * nn + zz * h.y;
    }
    {
        float rr = sigm(gir.z + ghr.z), zz = sigm(giz.z + ghz.z);
        float nn = tanhf(gin.z + rr * ghn.z);
        o.z = (1.f - zz) * nn + zz * h.z;
    }
    {
        float rr = sigm(gir.w + ghr.w), zz = sigm(giz.w + ghz.w);
        float nn = tanhf(gin.w + rr * ghn.w);
        o.w = (1.f - zz) * nn + zz * h.w;
    }
    ((float4*)g_rj)[idx] = o;
}

// ---------------- final assembly: single descriptor load -> payload -> store ----------------
__global__ void __launch_bounds__(256) assemble_kernel(
    float* __restrict__ out, const float* __restrict__ entity_table, int N)
{
    long long gid = (long long)blockIdx.x * blockDim.x + threadIdx.x;
    int lane = (int)(gid & 63);
    long long n = gid >> 6;
    if (n >= N) return;

    int c = g_src[n];                               // warp-uniform broadcast
    float4 v;
    if (c >= 0) {
        if (c & OBJ_FLAG) {
            v = ((const float4*)(g_objTable + (size_t)(c & (OBJ_FLAG - 1)) * DD))[lane];
        } else {
            v = __ldcs((const float4*)(entity_table + (size_t)c * DD) + lane);
        }
    } else if (c == -2) {
        v = ((const float4*)g_sub)[lane];
    } else {
        v = make_float4(0.f, 0.f, 0.f, 0.f);
    }
    __stcs((float4*)out + n * (DD / 4) + lane, v);
}

// ---------------- launch ----------------
extern "C" void kernel_launch(void* const* d_in, const int* in_sizes, int n_in,
                              void* d_out, int out_size)
{
    const float* enc          = (const float*)d_in[0];
    const float* mask         = (const float*)d_in[1];
    const float* entity_table = (const float*)d_in[2];
    const float* rel_table    = (const float*)d_in[3];
    const float* W_ih         = (const float*)d_in[4];
    const float* W_hh         = (const float*)d_in[5];
    const float* b_ih         = (const float*)d_in[6];
    const float* b_hh         = (const float*)d_in[7];
    const float* sub_W        = (const float*)d_in[8];
    const float* sub_b        = (const float*)d_in[9];
    const float* obj_W        = (const float*)d_in[10];
    const float* obj_b        = (const float*)d_in[11];
    const int*   rel_ids      = (const int*)d_in[12];
    const int*   tail_ids     = (const int*)d_in[13];
    const int*   tails_state  = (const int*)d_in[14];
    const int*   origin_ids   = (const int*)d_in[15];
    const int*   seed_p       = (const int*)d_in[16];
    float*       out          = (float*)d_out;

    int E = in_sizes[12];
    int R = in_sizes[3] / DD;
    int N = out_size / DD;

    float *ghp, *whp, *rjp, *owp, *otp;
    cudaGetSymbolAddress((void**)&ghp, g_gh);
    cudaGetSymbolAddress((void**)&whp, g_WhhT);
    cudaGetSymbolAddress((void**)&rjp, g_rj);
    cudaGetSymbolAddress((void**)&owp, g_objWT);
    cudaGetSymbolAddress((void**)&otp, g_objTable);

    // 1) transposes + g_src init + seed mark (fused)
    int initBlocks = 256 + (N + 1023) / 1024;
    init_kernel<<<initBlocks, dim3(32, 32)>>>(W_hh, obj_W, seed_p, N);

    // 2) scatter source descriptors (overwrites seed if seed is a tail, matching ref order)
    scatter_kernel<<<(E + 511) / 512, 512>>>(tail_ids, tails_state, origin_ids, rel_ids, E);

    // 3) prep chain as three parallel matvec stages
    matvecA_kernel<<<32, 256>>>(mask, sub_W, sub_b);
    matvecB_kernel<<<192, 256>>>(enc, W_ih, W_hh, b_ih, b_hh);
    matvecD_kernel<<<96, 256>>>(W_ih, b_ih);

    // 4) gh = rel_table @ W_hh.T + b_hh   [R,768]
    gemm_kernel<DD3, false><<<dim3(DD3 / 64, (R + 31) / 32), 256>>>(rel_table, whp, b_hh, ghp, R);

    // 5) GRU combine -> g_rj
    combine_kernel<<<(R * 64 + 255) / 256, 256>>>(rel_table, R);

    // 6) obj_table = tanh(g_rj @ obj_W.T + obj_b)  [R,256]
    gemm_kernel<DD, true><<<dim3(DD / 64, (R + 31) / 32), 256>>>(rjp, owp, obj_b, otp, R);

    // 7) final assembly
    long long rowThreads = (long long)N * 64;
    int asmBlocks = (int)((rowThreads + 255) / 256);
    assemble_kernel<<<asmBlocks, 256>>>(out, entity_table, N);
}

// round 7
// speedup vs baseline: 2.3056x; 1.0279x over previous
#include <cuda_runtime.h>
#include <math.h>

#define DD   256
#define DD3  768
#define OBJ_FLAG 0x40000000

// ---------------- device scratch ----------------
__device__ float g_sub[DD];                 // seed subject embedding
__device__ float g_gi0[DD3];                // enc @ W_ih.T + b_ih
__device__ float g_gh0[DD3];                // sub @ W_hh.T + b_hh
__device__ float g_gi[DD3];                 // r0 @ W_ih.T + b_ih (broadcast gi)
__device__ float g_WhhT[DD * DD3];          // W_hh transposed
__device__ float g_objWT[DD * DD];          // obj_W transposed
__device__ float g_gh[1024 * DD3];          // rel GEMM output [R,768]
__device__ float g_rj[1024 * DD];           // GRU output per relation [R,256]
__device__ float g_objTable[1024 * DD];     // obj embedding per relation [R,256]
__device__ int   g_src[1 << 19];            // node -> source descriptor

__device__ __forceinline__ float sigm(float x) { return 1.0f / (1.0f + expf(-x)); }

// ---------------- merged weight transposes ----------------
__global__ void transpose_kernel(const float* __restrict__ W_hh,
                                 const float* __restrict__ obj_W) {
    __shared__ float tile[32][33];
    int bx = blockIdx.x, by = blockIdx.y;
    if (by < 24) {
        int x = bx * 32 + threadIdx.x;
        int y = by * 32 + threadIdx.y;
        tile[threadIdx.y][threadIdx.x] = W_hh[y * DD + x];
        __syncthreads();
        int oj = by * 32 + threadIdx.x;
        int ok = bx * 32 + threadIdx.y;
        g_WhhT[ok * DD3 + oj] = tile[threadIdx.x][threadIdx.y];
    } else {
        int byy = by - 24;
        int x = bx * 32 + threadIdx.x;
        int y = byy * 32 + threadIdx.y;
        tile[threadIdx.y][threadIdx.x] = obj_W[y * DD + x];
        __syncthreads();
        int oj = byy * 32 + threadIdx.x;
        int ok = bx * 32 + threadIdx.y;
        g_objWT[ok * DD + oj] = tile[threadIdx.x][threadIdx.y];
    }
}

// ---------------- warp-per-row matvec stages ----------------
__global__ void __launch_bounds__(256) matvecA_kernel(
    const float* __restrict__ mask, const float* __restrict__ sub_W,
    const float* __restrict__ sub_b)
{
    __shared__ float4 xv[64];
    int tid = threadIdx.x, lane = tid & 31, warp = tid >> 5;
    if (tid < 64) xv[tid] = ((const float4*)mask)[tid];
    __syncthreads();
    int row = blockIdx.x * 8 + warp;
    const float4* w = (const float4*)(sub_W + (size_t)row * DD);
    float acc = 0.f;
    #pragma unroll
    for (int i = 0; i < 2; i++) {
        int k = lane + i * 32;
        float4 wv = w[k], x4 = xv[k];
        acc += wv.x * x4.x + wv.y * x4.y + wv.z * x4.z + wv.w * x4.w;
    }
    #pragma unroll
    for (int o = 16; o > 0; o >>= 1) acc += __shfl_down_sync(~0u, acc, o);
    if (lane == 0) g_sub[row] = tanhf(acc + sub_b[row]);
}

__global__ void __launch_bounds__(256) matvecB_kernel(
    const float* __restrict__ enc,
    const float* __restrict__ W_ih, const float* __restrict__ W_hh,
    const float* __restrict__ b_ih, const float* __restrict__ b_hh)
{
    __shared__ float4 xe[64], xs[64];
    int tid = threadIdx.x, lane = tid & 31, warp = tid >> 5;
    if (tid < 64) { xe[tid] = ((const float4*)enc)[tid]; xs[tid] = ((const float4*)g_sub)[tid]; }
    __syncthreads();
    int grow = blockIdx.x * 8 + warp;            // 0..1535
    bool isB = grow >= DD3;
    int row = isB ? grow - DD3 : grow;
    const float4* w = (const float4*)((isB ? W_hh : W_ih) + (size_t)row * DD);
    const float4* xv = isB ? xs : xe;
    float acc = 0.f;
    #pragma unroll
    for (int i = 0; i < 2; i++) {
        int k = lane + i * 32;
        float4 wv = w[k], x4 = xv[k];
        acc += wv.x * x4.x + wv.y * x4.y + wv.z * x4.z + wv.w * x4.w;
    }
    #pragma unroll
    for (int o = 16; o > 0; o >>= 1) acc += __shfl_down_sync(~0u, acc, o);
    if (lane == 0) {
        if (isB) g_gh0[row] = acc + b_hh[row];
        else     g_gi0[row] = acc + b_ih[row];
    }
}

__global__ void __launch_bounds__(256) matvecD_kernel(
    const float* __restrict__ W_ih, const float* __restrict__ b_ih)
{
    __shared__ float r0s[DD];
    int tid = threadIdx.x, lane = tid & 31, warp = tid >> 5;
    {
        float gi_r = g_gi0[tid],        gh_r = g_gh0[tid];
        float gi_z = g_gi0[DD + tid],   gh_z = g_gh0[DD + tid];
        float gi_n = g_gi0[2*DD + tid], gh_n = g_gh0[2*DD + tid];
        float r = sigm(gi_r + gh_r);
        float z = sigm(gi_z + gh_z);
        float n = tanhf(gi_n + r * gh_n);
        r0s[tid] = (1.0f - z) * n + z * g_sub[tid];
    }
    __syncthreads();
    int row = blockIdx.x * 8 + warp;             // 0..767
    const float4* w = (const float4*)(W_ih + (size_t)row * DD);
    const float4* xv = (const float4*)r0s;
    float acc = 0.f;
    #pragma unroll
    for (int i = 0; i < 2; i++) {
        int k = lane + i * 32;
        float4 wv = w[k], x4 = xv[k];
        acc += wv.x * x4.x + wv.y * x4.y + wv.z * x4.z + wv.w * x4.w;
    }
    #pragma unroll
    for (int o = 16; o > 0; o >>= 1) acc += __shfl_down_sync(~0u, acc, o);
    if (lane == 0) g_gi[row] = acc + b_ih[row];
}

// ---------------- seed mark + scatter ----------------
__global__ void seed_mark_kernel(const int* __restrict__ seed_p) {
    g_src[*seed_p] = -2;
}

__global__ void __launch_bounds__(512) scatter_kernel(
    const int* __restrict__ tail_ids, const int* __restrict__ tails_state,
    const int* __restrict__ origin_ids, const int* __restrict__ rel_ids, int E)
{
    int e = blockIdx.x * blockDim.x + threadIdx.x;
    if (e >= E) return;
    int code = (__ldg(tails_state + e) == 1) ? __ldg(origin_ids + e)
                                             : (__ldg(rel_ids + e) | OBJ_FLAG);
    g_src[__ldg(tail_ids + e)] = code;
}

// ---------------- tiled GEMM 32x64 ----------------
template<int NCOLS, bool DOTANH>
__global__ void __launch_bounds__(256) gemm_kernel(
    const float* __restrict__ A, const float* __restrict__ B,
    const float* __restrict__ bias, float* __restrict__ C, int M)
{
    __shared__ float As[32][36];
    __shared__ float Bs[32][68];
    int tid = threadIdx.x;
    int tx = tid & 15, ty = tid >> 4;
    int rbase = blockIdx.y * 32;
    int cbase = blockIdx.x * 64;
    float acc[2][4] = {};

    for (int k0 = 0; k0 < DD; k0 += 32) {
        {
            int ar = tid >> 3;
            int ac = (tid & 7) << 2;
            int gr = rbase + ar;
            float4 av = (gr < M) ? *(const float4*)(A + (size_t)gr * DD + k0 + ac)
                                 : make_float4(0.f, 0.f, 0.f, 0.f);
            *(float4*)&As[ar][ac] = av;
        }
        #pragma unroll
        for (int i = 0; i < 2; i++) {
            int idx = tid + i * 256;
            int bk = idx >> 4;
            int bc = (idx & 15) << 2;
            float4 bv = *(const float4*)(B + (size_t)(k0 + bk) * NCOLS + cbase + bc);
            *(float4*)&Bs[bk][bc] = bv;
        }
        __syncthreads();
        #pragma unroll
        for (int kk = 0; kk < 32; kk++) {
            float a0 = As[ty * 2 + 0][kk];
            float a1 = As[ty * 2 + 1][kk];
            float4 b = *(const float4*)&Bs[kk][tx * 4];
            acc[0][0] = fmaf(a0, b.x, acc[0][0]); acc[0][1] = fmaf(a0, b.y, acc[0][1]);
            acc[0][2] = fmaf(a0, b.z, acc[0][2]); acc[0][3] = fmaf(a0, b.w, acc[0][3]);
            acc[1][0] = fmaf(a1, b.x, acc[1][0]); acc[1][1] = fmaf(a1, b.y, acc[1][1]);
            acc[1][2] = fmaf(a1, b.z, acc[1][2]); acc[1][3] = fmaf(a1, b.w, acc[1][3]);
        }
        __syncthreads();
    }

    int col = cbase + tx * 4;
    float4 bv = *(const float4*)(bias + col);
    #pragma unroll
    for (int i = 0; i < 2; i++) {
        int gr = rbase + ty * 2 + i;
        if (gr < M) {
            float4 v;
            v.x = acc[i][0] + bv.x; v.y = acc[i][1] + bv.y;
            v.z = acc[i][2] + bv.z; v.w = acc[i][3] + bv.w;
            if (DOTANH) { v.x = tanhf(v.x); v.y = tanhf(v.y); v.z = tanhf(v.z); v.w = tanhf(v.w); }
            *(float4*)(C + (size_t)gr * NCOLS + col) = v;
        }
    }
}

// ---------------- GRU gate combine (float4) ----------------
__global__ void __launch_bounds__(256) combine_kernel(const float* __restrict__ rel_table, int R) {
    int idx = blockIdx.x * blockDim.x + threadIdx.x;
    if (idx >= R * 64) return;
    int r = idx >> 6, t4 = idx & 63;
    const float4* gi4 = (const float4*)g_gi;
    const float4* gh4 = (const float4*)(g_gh + (size_t)r * DD3);
    float4 gir = gi4[t4],        ghr = gh4[t4];
    float4 giz = gi4[64 + t4],   ghz = gh4[64 + t4];
    float4 gin = gi4[128 + t4],  ghn = gh4[128 + t4];
    float4 h   = ((const float4*)rel_table)[(size_t)r * 64 + t4];
    float4 o;
    { float rr = sigm(gir.x + ghr.x), zz = sigm(giz.x + ghz.x);
      float nn = tanhf(gin.x + rr * ghn.x); o.x = (1.f - zz) * nn + zz * h.x; }
    { float rr = sigm(gir.y + ghr.y), zz = sigm(giz.y + ghz.y);
      float nn = tanhf(gin.y + rr * ghn.y); o.y = (1.f - zz) * nn + zz * h.y; }
    { float rr = sigm(gir.z + ghr.z), zz = sigm(giz.z + ghz.z);
      float nn = tanhf(gin.z + rr * ghn.z); o.z = (1.f - zz) * nn + zz * h.z; }
    { float rr = sigm(gir.w + ghr.w), zz = sigm(giz.w + ghz.w);
      float nn = tanhf(gin.w + rr * ghn.w); o.w = (1.f - zz) * nn + zz * h.w; }
    ((float4*)g_rj)[idx] = o;
}

// ---------------- final assembly ----------------
__global__ void __launch_bounds__(256) assemble_kernel(
    float* __restrict__ out, const float* __restrict__ entity_table, int N)
{
    long long gid = (long long)blockIdx.x * blockDim.x + threadIdx.x;
    int lane = (int)(gid & 63);
    long long n = gid >> 6;
    if (n >= N) return;

    int c = g_src[n];
    float4 v;
    if (c >= 0) {
        if (c & OBJ_FLAG) {
            v = ((const float4*)(g_objTable + (size_t)(c & (OBJ_FLAG - 1)) * DD))[lane];
        } else {
            v = __ldcs((const float4*)(entity_table + (size_t)c * DD) + lane);
        }
    } else if (c == -2) {
        v = ((const float4*)g_sub)[lane];
    } else {
        v = make_float4(0.f, 0.f, 0.f, 0.f);
    }
    __stcs((float4*)out + n * (DD / 4) + lane, v);
}

// ---------------- launch: 3-way DAG fork, identical kernel bodies ----------------
extern "C" void kernel_launch(void* const* d_in, const int* in_sizes, int n_in,
                              void* d_out, int out_size)
{
    const float* enc          = (const float*)d_in[0];
    const float* mask         = (const float*)d_in[1];
    const float* entity_table = (const float*)d_in[2];
    const float* rel_table    = (const float*)d_in[3];
    const float* W_ih         = (const float*)d_in[4];
    const float* W_hh         = (const float*)d_in[5];
    const float* b_ih         = (const float*)d_in[6];
    const float* b_hh         = (const float*)d_in[7];
    const float* sub_W        = (const float*)d_in[8];
    const float* sub_b        = (const float*)d_in[9];
    const float* obj_W        = (const float*)d_in[10];
    const float* obj_b        = (const float*)d_in[11];
    const int*   rel_ids      = (const int*)d_in[12];
    const int*   tail_ids     = (const int*)d_in[13];
    const int*   tails_state  = (const int*)d_in[14];
    const int*   origin_ids   = (const int*)d_in[15];
    const int*   seed_p       = (const int*)d_in[16];
    float*       out          = (float*)d_out;

    int E = in_sizes[12];
    int R = in_sizes[3] / DD;
    int N = out_size / DD;

    static cudaStream_t s1 = nullptr, s2 = nullptr;
    static cudaEvent_t evFork = nullptr, evGi = nullptr, evSrc = nullptr, evSubA = nullptr;
    if (!s1) {
        cudaStreamCreateWithFlags(&s1, cudaStreamNonBlocking);
        cudaStreamCreateWithFlags(&s2, cudaStreamNonBlocking);
        cudaEventCreateWithFlags(&evFork, cudaEventDisableTiming);
        cudaEventCreateWithFlags(&evGi,   cudaEventDisableTiming);
        cudaEventCreateWithFlags(&evSrc,  cudaEventDisableTiming);
        cudaEventCreateWithFlags(&evSubA, cudaEventDisableTiming);
    }

    float *ghp, *whp, *rjp, *owp, *otp;
    int *srcp;
    cudaGetSymbolAddress((void**)&ghp, g_gh);
    cudaGetSymbolAddress((void**)&whp, g_WhhT);
    cudaGetSymbolAddress((void**)&rjp, g_rj);
    cudaGetSymbolAddress((void**)&owp, g_objWT);
    cudaGetSymbolAddress((void**)&otp, g_objTable);
    cudaGetSymbolAddress((void**)&srcp, g_src);

    // ---- fork s1 (gi chain) and s2 (src map) off the capture stream ----
    cudaEventRecord(evFork, 0);
    cudaStreamWaitEvent(s1, evFork, 0);
    cudaStreamWaitEvent(s2, evFork, 0);

    // ---- s0: weights path -> gemm768 ----
    transpose_kernel<<<dim3(8, 32), dim3(32, 32)>>>(W_hh, obj_W);
    gemm_kernel<DD3, false><<<dim3(DD3 / 64, (R + 31) / 32), 256>>>(rel_table, whp, b_hh, ghp, R);

    // ---- s1: gi chain (A -> B -> D) ----
    matvecA_kernel<<<32, 256, 0, s1>>>(mask, sub_W, sub_b);
    matvecB_kernel<<<192, 256, 0, s1>>>(enc, W_ih, W_hh, b_ih, b_hh);
    matvecD_kernel<<<96, 256, 0, s1>>>(W_ih, b_ih);
    cudaEventRecord(evGi, s1);

    // ---- s2: src map (memset -1 -> seed -> scatter) ----
    cudaMemsetAsync(srcp, 0xFF, (size_t)N * sizeof(int), s2);
    seed_mark_kernel<<<1, 1, 0, s2>>>(seed_p);
    scatter_kernel<<<(E + 511) / 512, 512, 0, s2>>>(tail_ids, tails_state, origin_ids, rel_ids, E);
    cudaEventRecord(evSrc, s2);

    // ---- s0: combine (needs gemm768 + gi) -> objGEMM -> assemble (needs src + sub) ----
    cudaStreamWaitEvent(0, evGi, 0);
    combine_kernel<<<(R * 64 + 255) / 256, 256>>>(rel_table, R);
    gemm_kernel<DD, true><<<dim3(DD / 64, (R + 31) / 32), 256>>>(rjp, owp, obj_b, otp, R);
    cudaStreamWaitEvent(0, evSrc, 0);
    long long rowThreads = (long long)N * 64;
    int asmBlocks = (int)((rowThreads + 255) / 256);
    assemble_kernel<<<asmBlocks, 256>>>(out, entity_table, N);
}

// round 8
// speedup vs baseline: 2.3573x; 1.0224x over previous
#include <cuda_runtime.h>
#include <math.h>

#define DD   256
#define DD3  768
#define OBJ_FLAG 0x40000000

// ---------------- device scratch ----------------
__device__ float g_sub[DD];                 // seed subject embedding
__device__ float g_gi0[DD3];                // enc @ W_ih.T + b_ih
__device__ float g_gh0[DD3];                // sub @ W_hh.T + b_hh
__device__ float g_gi[DD3];                 // r0 @ W_ih.T + b_ih (broadcast gi)
__device__ float g_rj[1024 * DD];           // GRU output per relation [R,256]
__device__ float g_objTable[1024 * DD];     // obj embedding per relation [R,256]
__device__ int   g_src[1 << 19];            // node -> source descriptor

__device__ __forceinline__ float sigm(float x) { return 1.0f / (1.0f + expf(-x)); }

// ---------------- warp-per-row matvec stages ----------------
__global__ void __launch_bounds__(256) matvecA_kernel(
    const float* __restrict__ mask, const float* __restrict__ sub_W,
    const float* __restrict__ sub_b)
{
    __shared__ float4 xv[64];
    int tid = threadIdx.x, lane = tid & 31, warp = tid >> 5;
    if (tid < 64) xv[tid] = ((const float4*)mask)[tid];
    __syncthreads();
    int row = blockIdx.x * 8 + warp;
    const float4* w = (const float4*)(sub_W + (size_t)row * DD);
    float acc = 0.f;
    #pragma unroll
    for (int i = 0; i < 2; i++) {
        int k = lane + i * 32;
        float4 wv = w[k], x4 = xv[k];
        acc += wv.x * x4.x + wv.y * x4.y + wv.z * x4.z + wv.w * x4.w;
    }
    #pragma unroll
    for (int o = 16; o > 0; o >>= 1) acc += __shfl_down_sync(~0u, acc, o);
    if (lane == 0) g_sub[row] = tanhf(acc + sub_b[row]);
}

__global__ void __launch_bounds__(256) matvecB_kernel(
    const float* __restrict__ enc,
    const float* __restrict__ W_ih, const float* __restrict__ W_hh,
    const float* __restrict__ b_ih, const float* __restrict__ b_hh)
{
    __shared__ float4 xe[64], xs[64];
    int tid = threadIdx.x, lane = tid & 31, warp = tid >> 5;
    if (tid < 64) { xe[tid] = ((const float4*)enc)[tid]; xs[tid] = ((const float4*)g_sub)[tid]; }
    __syncthreads();
    int grow = blockIdx.x * 8 + warp;            // 0..1535
    bool isB = grow >= DD3;
    int row = isB ? grow - DD3 : grow;
    const float4* w = (const float4*)((isB ? W_hh : W_ih) + (size_t)row * DD);
    const float4* xv = isB ? xs : xe;
    float acc = 0.f;
    #pragma unroll
    for (int i = 0; i < 2; i++) {
        int k = lane + i * 32;
        float4 wv = w[k], x4 = xv[k];
        acc += wv.x * x4.x + wv.y * x4.y + wv.z * x4.z + wv.w * x4.w;
    }
    #pragma unroll
    for (int o = 16; o > 0; o >>= 1) acc += __shfl_down_sync(~0u, acc, o);
    if (lane == 0) {
        if (isB) g_gh0[row] = acc + b_hh[row];
        else     g_gi0[row] = acc + b_ih[row];
    }
}

__global__ void __launch_bounds__(256) matvecD_kernel(
    const float* __restrict__ W_ih, const float* __restrict__ b_ih)
{
    __shared__ float r0s[DD];
    int tid = threadIdx.x, lane = tid & 31, warp = tid >> 5;
    {
        float gi_r = g_gi0[tid],        gh_r = g_gh0[tid];
        float gi_z = g_gi0[DD + tid],   gh_z = g_gh0[DD + tid];
        float gi_n = g_gi0[2*DD + tid], gh_n = g_gh0[2*DD + tid];
        float r = sigm(gi_r + gh_r);
        float z = sigm(gi_z + gh_z);
        float n = tanhf(gi_n + r * gh_n);
        r0s[tid] = (1.0f - z) * n + z * g_sub[tid];
    }
    __syncthreads();
    int row = blockIdx.x * 8 + warp;             // 0..767
    const float4* w = (const float4*)(W_ih + (size_t)row * DD);
    const float4* xv = (const float4*)r0s;
    float acc = 0.f;
    #pragma unroll
    for (int i = 0; i < 2; i++) {
        int k = lane + i * 32;
        float4 wv = w[k], x4 = xv[k];
        acc += wv.x * x4.x + wv.y * x4.y + wv.z * x4.z + wv.w * x4.w;
    }
    #pragma unroll
    for (int o = 16; o > 0; o >>= 1) acc += __shfl_down_sync(~0u, acc, o);
    if (lane == 0) g_gi[row] = acc + b_ih[row];
}

// ---------------- scatter: resolve per-edge source descriptor ----------------
__global__ void __launch_bounds__(512) scatter_kernel(
    const int* __restrict__ tail_ids, const int* __restrict__ tails_state,
    const int* __restrict__ origin_ids, const int* __restrict__ rel_ids, int E)
{
    int e = blockIdx.x * blockDim.x + threadIdx.x;
    if (e >= E) return;
    int code = (__ldg(tails_state + e) == 1) ? __ldg(origin_ids + e)
                                             : (__ldg(rel_ids + e) | OBJ_FLAG);
    g_src[__ldg(tail_ids + e)] = code;
}

// ---------------- fused: gh GEMM (3 gates per block) + GRU combine -> g_rj ----------------
// grid (4, ceil(R/32)). Block owns rel rows rbase..+32, gate-col chunk j0..j0+64 for ALL 3 gates.
// Reads W_hh row-major directly (transpose folded into smem store).
__global__ void __launch_bounds__(256) relgemm_kernel(
    const float* __restrict__ rel_table, const float* __restrict__ W_hh,
    const float* __restrict__ b_hh, int R)
{
    __shared__ float As[32][36];
    __shared__ float Bs[3][32][68];
    int tid = threadIdx.x;
    int tx = tid & 15, ty = tid >> 4;
    int rbase = blockIdx.y * 32;
    int j0 = blockIdx.x * 64;
    float acc[3][2][4] = {};

    for (int k0 = 0; k0 < DD; k0 += 32) {
        {   // A tile: rel_table rows
            int ar = tid >> 3;
            int ac = (tid & 7) << 2;
            int gr = rbase + ar;
            float4 av = (gr < R) ? *(const float4*)(rel_table + (size_t)gr * DD + k0 + ac)
                                 : make_float4(0.f, 0.f, 0.f, 0.f);
            *(float4*)&As[ar][ac] = av;
        }
        #pragma unroll
        for (int i = 0; i < 6; i++) {  // B tiles: 192 j-rows x 32 k, transposed store
            int idx = tid + i * 256;
            int jrow = idx >> 3;       // 0..191
            int kc = (idx & 7) << 2;
            int gate = jrow >> 6;
            int jj = jrow & 63;
            float4 w4 = *(const float4*)(W_hh + (size_t)(gate * DD + j0 + jj) * DD + k0 + kc);
            Bs[gate][kc + 0][jj] = w4.x;
            Bs[gate][kc + 1][jj] = w4.y;
            Bs[gate][kc + 2][jj] = w4.z;
            Bs[gate][kc + 3][jj] = w4.w;
        }
        __syncthreads();
        #pragma unroll
        for (int kk = 0; kk < 32; kk++) {
            float a0 = As[ty][kk];
            float a1 = As[ty + 16][kk];
            #pragma unroll
            for (int g = 0; g < 3; g++) {
                float4 b = *(const float4*)&Bs[g][kk][tx * 4];
                acc[g][0][0] = fmaf(a0, b.x, acc[g][0][0]); acc[g][0][1] = fmaf(a0, b.y, acc[g][0][1]);
                acc[g][0][2] = fmaf(a0, b.z, acc[g][0][2]); acc[g][0][3] = fmaf(a0, b.w, acc[g][0][3]);
                acc[g][1][0] = fmaf(a1, b.x, acc[g][1][0]); acc[g][1][1] = fmaf(a1, b.y, acc[g][1][1]);
                acc[g][1][2] = fmaf(a1, b.z, acc[g][1][2]); acc[g][1][3] = fmaf(a1, b.w, acc[g][1][3]);
            }
        }
        __syncthreads();
    }

    // epilogue: gh -> GRU combine -> rj
    int col = j0 + tx * 4;
    float4 bhr = *(const float4*)(b_hh + col);
    float4 bhz = *(const float4*)(b_hh + DD + col);
    float4 bhn = *(const float4*)(b_hh + 2 * DD + col);
    float4 gir = *(const float4*)(g_gi + col);
    float4 giz = *(const float4*)(g_gi + DD + col);
    float4 gin = *(const float4*)(g_gi + 2 * DD + col);
    #pragma unroll
    for (int i = 0; i < 2; i++) {
        int r = rbase + ty + i * 16;
        if (r < R) {
            float4 h = *(const float4*)(rel_table + (size_t)r * DD + col);
            float ghr[4] = { acc[0][i][0] + bhr.x, acc[0][i][1] + bhr.y, acc[0][i][2] + bhr.z, acc[0][i][3] + bhr.w };
            float ghz[4] = { acc[1][i][0] + bhz.x, acc[1][i][1] + bhz.y, acc[1][i][2] + bhz.z, acc[1][i][3] + bhz.w };
            float ghn[4] = { acc[2][i][0] + bhn.x, acc[2][i][1] + bhn.y, acc[2][i][2] + bhn.z, acc[2][i][3] + bhn.w };
            float gi_r[4] = { gir.x, gir.y, gir.z, gir.w };
            float gi_z[4] = { giz.x, giz.y, giz.z, giz.w };
            float gi_n[4] = { gin.x, gin.y, gin.z, gin.w };
            float hh[4] = { h.x, h.y, h.z, h.w };
            float o[4];
            #pragma unroll
            for (int q = 0; q < 4; q++) {
                float rr = sigm(gi_r[q] + ghr[q]);
                float zz = sigm(gi_z[q] + ghz[q]);
                float nn = tanhf(gi_n[q] + rr * ghn[q]);
                o[q] = (1.f - zz) * nn + zz * hh[q];
            }
            *(float4*)(g_rj + (size_t)r * DD + col) = make_float4(o[0], o[1], o[2], o[3]);
        }
    }
}

// ---------------- obj GEMM: objTable = tanh(rj @ obj_W.T + obj_b), direct W read ----------------
__global__ void __launch_bounds__(256) objgemm_kernel(
    const float* __restrict__ obj_W, const float* __restrict__ obj_b, int R)
{
    __shared__ float As[32][36];
    __shared__ float Bs[32][68];
    int tid = threadIdx.x;
    int tx = tid & 15, ty = tid >> 4;
    int rbase = blockIdx.y * 32;
    int cbase = blockIdx.x * 64;
    float acc[2][4] = {};

    for (int k0 = 0; k0 < DD; k0 += 32) {
        {
            int ar = tid >> 3;
            int ac = (tid & 7) << 2;
            int gr = rbase + ar;
            float4 av = (gr < R) ? *(const float4*)(g_rj + (size_t)gr * DD + k0 + ac)
                                 : make_float4(0.f, 0.f, 0.f, 0.f);
            *(float4*)&As[ar][ac] = av;
        }
        #pragma unroll
        for (int i = 0; i < 2; i++) {  // 64 j-rows x 32 k, transposed store
            int idx = tid + i * 256;
            int jj = idx >> 3;         // 0..63
            int kc = (idx & 7) << 2;
            float4 w4 = *(const float4*)(obj_W + (size_t)(cbase + jj) * DD + k0 + kc);
            Bs[kc + 0][jj] = w4.x;
            Bs[kc + 1][jj] = w4.y;
            Bs[kc + 2][jj] = w4.z;
            Bs[kc + 3][jj] = w4.w;
        }
        __syncthreads();
        #pragma unroll
        for (int kk = 0; kk < 32; kk++) {
            float a0 = As[ty][kk];
            float a1 = As[ty + 16][kk];
            float4 b = *(const float4*)&Bs[kk][tx * 4];
            acc[0][0] = fmaf(a0, b.x, acc[0][0]); acc[0][1] = fmaf(a0, b.y, acc[0][1]);
            acc[0][2] = fmaf(a0, b.z, acc[0][2]); acc[0][3] = fmaf(a0, b.w, acc[0][3]);
            acc[1][0] = fmaf(a1, b.x, acc[1][0]); acc[1][1] = fmaf(a1, b.y, acc[1][1]);
            acc[1][2] = fmaf(a1, b.z, acc[1][2]); acc[1][3] = fmaf(a1, b.w, acc[1][3]);
        }
        __syncthreads();
    }

    int col = cbase + tx * 4;
    float4 bv = *(const float4*)(obj_b + col);
    #pragma unroll
    for (int i = 0; i < 2; i++) {
        int r = rbase + ty + i * 16;
        if (r < R) {
            float4 v;
            v.x = tanhf(acc[i][0] + bv.x); v.y = tanhf(acc[i][1] + bv.y);
            v.z = tanhf(acc[i][2] + bv.z); v.w = tanhf(acc[i][3] + bv.w);
            *(float4*)(g_objTable + (size_t)r * DD + col) = v;
        }
    }
}

// ---------------- final assembly: 32 threads/row, 2 rows/thread (MLP 4) ----------------
__device__ __forceinline__ void fetch_row(
    int c, long long n, int sd, const float* __restrict__ et, int lane,
    float4& a, float4& b)
{
    if (c >= 0) {
        if (c & OBJ_FLAG) {
            const float4* p = (const float4*)(g_objTable + (size_t)(c & (OBJ_FLAG - 1)) * DD);
            a = p[lane * 2]; b = p[lane * 2 + 1];
        } else {
            const float4* p = (const float4*)(et + (size_t)c * DD);
            a = __ldcs(p + lane * 2); b = __ldcs(p + lane * 2 + 1);
        }
    } else if ((int)n == sd) {
        const float4* p = (const float4*)g_sub;
        a = p[lane * 2]; b = p[lane * 2 + 1];
    } else {
        a = make_float4(0.f, 0.f, 0.f, 0.f);
        b = a;
    }
}

__global__ void __launch_bounds__(256) assemble_kernel(
    float* __restrict__ out, const float* __restrict__ entity_table,
    const int* __restrict__ seed_p, int N)
{
    long long gid = (long long)blockIdx.x * blockDim.x + threadIdx.x;
    int lane = (int)(gid & 31);
    long long i = gid >> 5;
    long long half = (N + 1) >> 1;
    if (i >= half) return;

    long long n0 = i, n1 = i + half;
    bool has1 = n1 < N;
    int sd = __ldg(seed_p);
    int c0 = g_src[n0];
    int c1 = has1 ? g_src[n1] : -1;

    float4 a0, b0, a1, b1;
    fetch_row(c0, n0, sd, entity_table, lane, a0, b0);
    if (has1) fetch_row(c1, n1, sd, entity_table, lane, a1, b1);

    float4* o0 = (float4*)out + n0 * (DD / 4);
    __stcs(o0 + lane * 2, a0);
    __stcs(o0 + lane * 2 + 1, b0);
    if (has1) {
        float4* o1 = (float4*)out + n1 * (DD / 4);
        __stcs(o1 + lane * 2, a1);
        __stcs(o1 + lane * 2 + 1, b1);
    }
}

// ---------------- launch ----------------
extern "C" void kernel_launch(void* const* d_in, const int* in_sizes, int n_in,
                              void* d_out, int out_size)
{
    const float* enc          = (const float*)d_in[0];
    const float* mask         = (const float*)d_in[1];
    const float* entity_table = (const float*)d_in[2];
    const float* rel_table    = (const float*)d_in[3];
    const float* W_ih         = (const float*)d_in[4];
    const float* W_hh         = (const float*)d_in[5];
    const float* b_ih         = (const float*)d_in[6];
    const float* b_hh         = (const float*)d_in[7];
    const float* sub_W        = (const float*)d_in[8];
    const float* sub_b        = (const float*)d_in[9];
    const float* obj_W        = (const float*)d_in[10];
    const float* obj_b        = (const float*)d_in[11];
    const int*   rel_ids      = (const int*)d_in[12];
    const int*   tail_ids     = (const int*)d_in[13];
    const int*   tails_state  = (const int*)d_in[14];
    const int*   origin_ids   = (const int*)d_in[15];
    const int*   seed_p       = (const int*)d_in[16];
    float*       out          = (float*)d_out;

    int E = in_sizes[12];
    int R = in_sizes[3] / DD;
    int N = out_size / DD;

    static cudaStream_t s2 = nullptr;
    static cudaEvent_t evFork = nullptr, evSrc = nullptr;
    if (!s2) {
        cudaStreamCreateWithFlags(&s2, cudaStreamNonBlocking);
        cudaEventCreateWithFlags(&evFork, cudaEventDisableTiming);
        cudaEventCreateWithFlags(&evSrc,  cudaEventDisableTiming);
    }

    int* srcp;
    cudaGetSymbolAddress((void**)&srcp, g_src);

    // ---- s2: src map (memset -1 -> scatter); seed handled inside assemble ----
    cudaEventRecord(evFork, 0);
    cudaStreamWaitEvent(s2, evFork, 0);
    cudaMemsetAsync(srcp, 0xFF, (size_t)N * sizeof(int), s2);
    scatter_kernel<<<(E + 511) / 512, 512, 0, s2>>>(tail_ids, tails_state, origin_ids, rel_ids, E);
    cudaEventRecord(evSrc, s2);

    // ---- s0: gi chain -> fused rel GEMM+combine -> obj GEMM ----
    matvecA_kernel<<<32, 256>>>(mask, sub_W, sub_b);
    matvecB_kernel<<<192, 256>>>(enc, W_ih, W_hh, b_ih, b_hh);
    matvecD_kernel<<<96, 256>>>(W_ih, b_ih);
    relgemm_kernel<<<dim3(4, (R + 31) / 32), 256>>>(rel_table, W_hh, b_hh, R);
    objgemm_kernel<<<dim3(4, (R + 31) / 32), 256>>>(obj_W, obj_b, R);

    // ---- assemble (needs src map + objTable + g_sub) ----
    cudaStreamWaitEvent(0, evSrc, 0);
    long long half = ((long long)N + 1) >> 1;
    long long threads = half * 32;
    int asmBlocks = (int)((threads + 255) / 256);
    assemble_kernel<<<asmBlocks, 256>>>(out, entity_table, seed_p, N);
}